// round 12
// baseline (speedup 1.0000x reference)
#include <cuda_runtime.h>
#include <cuda_fp16.h>
#include <cstdint>

// Problem constants
#define BATCH 2
#define MQ    4096
#define CCH   256
#define NPIX  4096

// -------- scratch (device globals = allowed scratch) --------
__device__ __half g_a[BATCH * MQ * CCH];       // fp16 fmap1 (4 MB)
__device__ __half g_bT[BATCH * NPIX * CCH];    // fp16 fmap2^T (pixel, ch) level 0 (4 MB)
__device__ __half g_bT1[BATCH * 1024 * CCH];   // pooled pyramid, transposed fp16
__device__ __half g_bT2[BATCH * 256 * CCH];
__device__ __half g_bT3[BATCH * 64 * CCH];
__device__ float g_corr1[BATCH * MQ * 1024];   // 33 MB
__device__ float g_corr2[BATCH * MQ * 256];
__device__ float g_corr3[BATCH * MQ * 64];

// -------- helpers --------
__device__ __forceinline__ uint32_t smem_u32(const void* p) {
    uint32_t a;
    asm("{ .reg .u64 t; cvta.to.shared.u64 t, %1; cvt.u32.u64 %0, t; }"
        : "=r"(a) : "l"(p));
    return a;
}
__device__ __forceinline__ void cp16(uint32_t dst, const void* src) {
    asm volatile("cp.async.cg.shared.global [%0], [%1], 16;\n"
                 :: "r"(dst), "l"(src));
}
// zero-fill variant: src-size 0 -> 16 zero bytes (src not dereferenced)
__device__ __forceinline__ void cp16p(uint32_t dst, const void* src, bool v) {
    int sz = v ? 16 : 0;
    asm volatile("cp.async.cg.shared.global [%0], [%1], 16, %2;\n"
                 :: "r"(dst), "l"(src), "r"(sz));
}
#define CP_COMMIT() asm volatile("cp.async.commit_group;\n" ::: "memory")
#define CP_WAIT1()  asm volatile("cp.async.wait_group 1;\n" ::: "memory")
#define CP_WAIT0()  asm volatile("cp.async.wait_group 0;\n" ::: "memory")

__device__ __forceinline__ void ldsm_x4(uint32_t* r, uint32_t addr) {
    asm volatile("ldmatrix.sync.aligned.m8n8.x4.shared.b16 {%0,%1,%2,%3}, [%4];"
        : "=r"(r[0]), "=r"(r[1]), "=r"(r[2]), "=r"(r[3]) : "r"(addr));
}
__device__ __forceinline__ void mma_f16(float* d, const uint32_t* a, const uint32_t* b) {
    asm volatile(
        "mma.sync.aligned.m16n8k16.row.col.f32.f16.f16.f32 "
        "{%0,%1,%2,%3}, {%4,%5,%6,%7}, {%8,%9}, {%0,%1,%2,%3};\n"
        : "+f"(d[0]), "+f"(d[1]), "+f"(d[2]), "+f"(d[3])
        : "r"(a[0]), "r"(a[1]), "r"(a[2]), "r"(a[3]),
          "r"(b[0]), "r"(b[1]));
}

// ---------------------------------------------------------------------------
// Kernel 0a: fmap1 -> fp16 g_a (elementwise)
// ---------------------------------------------------------------------------
__global__ void convA_kernel(const float* __restrict__ f1) {
    size_t i = ((size_t)blockIdx.x * 256 + threadIdx.x) * 4;
    float4 v = *(const float4*)(f1 + i);
    __half2 lo = __floats2half2_rn(v.x, v.y);
    __half2 hi = __floats2half2_rn(v.z, v.w);
    *(uint2*)&g_a[i] = make_uint2(*(uint32_t*)&lo, *(uint32_t*)&hi);
}

// ---------------------------------------------------------------------------
// Kernel 0b: fmap2 (B, C, NPIX) -> g_bT (B, NPIX, C) fp16, 32x32 SMEM tiles
// ---------------------------------------------------------------------------
__global__ void transB_kernel(const float* __restrict__ f2) {
    __shared__ float tile[32][33];
    const int b  = blockIdx.z;
    const int x0 = blockIdx.x * 32;   // pixel
    const int c0 = blockIdx.y * 32;   // channel
    const int tx = threadIdx.x, ty = threadIdx.y;   // 32 x 8
    const float* src = f2 + (size_t)b * CCH * NPIX;
#pragma unroll
    for (int i = 0; i < 4; i++)
        tile[ty + 8 * i][tx] = src[(size_t)(c0 + ty + 8 * i) * NPIX + x0 + tx];
    __syncthreads();
    __half* dst = g_bT + (size_t)b * NPIX * CCH;
#pragma unroll
    for (int i = 0; i < 4; i++)
        dst[(size_t)(x0 + ty + 8 * i) * CCH + c0 + tx] =
            __float2half_rn(tile[tx][ty + 8 * i]);
}

// ---------------------------------------------------------------------------
// Kernel 0c: pooled fmap2 pyramid, transposed fp16. Block per (b, ch) plane.
// pool commutes with the channel dot, so corr_lvl = fmap1 . pool^lvl(fmap2).
// ---------------------------------------------------------------------------
__global__ void pyrT_kernel(const float* __restrict__ f2) {
    const int plane = blockIdx.x;            // b*256 + c
    const int b = plane >> 8, c = plane & 255;
    const float* src = f2 + (size_t)plane * 4096;
    __shared__ float s1[1024];
    __shared__ float s2[256];
    const int tid = threadIdx.x;
#pragma unroll
    for (int i = 0; i < 4; i++) {
        int idx = tid + 256 * i;
        int x = idx & 31, y = idx >> 5;
        const float* p = src + (2 * y) * 64 + 2 * x;
        float v = 0.25f * (p[0] + p[1] + p[64] + p[65]);
        s1[idx] = v;
        g_bT1[((size_t)(b << 10) + idx) * CCH + c] = __float2half_rn(v);
    }
    __syncthreads();
    {
        int x = tid & 15, y = tid >> 4;
        const float* p = s1 + (2 * y) * 32 + 2 * x;
        float v = 0.25f * (p[0] + p[1] + p[32] + p[33]);
        s2[tid] = v;
        g_bT2[((size_t)(b << 8) + tid) * CCH + c] = __float2half_rn(v);
    }
    __syncthreads();
    if (tid < 64) {
        int x = tid & 7, y = tid >> 3;
        const float* p = s2 + (2 * y) * 16 + 2 * x;
        float v = 0.25f * (p[0] + p[1] + p[16] + p[17]);
        g_bT3[((size_t)(b << 6) + tid) * CCH + c] = __float2half_rn(v);
    }
}

// ---------------------------------------------------------------------------
// Kernel 1: corr_lvl[b] = A[b] (4096x256) @ pooledB[b]^T for lvl 1..3.
// fp16 mma m16n8k16 + ldmatrix, CTA tile 128x128, K-chunks 64, 3-stage
// cp.async pipeline. Grid x: 0-7 -> l1 n-tiles, 8-9 -> l2, 10 -> l3.
// ---------------------------------------------------------------------------
#define KC 64
#define ROWB 144
#define A_BYTES  (128 * ROWB)
#define B_BYTES  (128 * ROWB)
#define STAGE_B  (A_BYTES + B_BYTES)
#define SMEM_T   (3 * STAGE_B)            // 110592

__global__ void __launch_bounds__(256, 1)
corr_gemm() {
    extern __shared__ char smem[];
    const uint32_t sb = smem_u32(smem);
    const int tid = threadIdx.x;
    const int warpId = tid >> 5, lane = tid & 31;
    const int g  = lane >> 2;
    const int tg = lane & 3;
    const int mWarp = (warpId >> 2) * 64;
    const int nWarp = (warpId & 3) * 32;

    const int b     = blockIdx.z;
    const int mBase = blockIdx.y * 128;

    const int x = blockIdx.x;
    int lvl, nt;
    if (x < 8)       { lvl = 1; nt = x; }
    else if (x < 10) { lvl = 2; nt = x - 8; }
    else             { lvl = 3; nt = 0; }
    const int Npix = 4096 >> (2 * lvl);          // 1024 / 256 / 64
    const int nBase = nt * 128;
    const __half* Bp = (lvl == 1) ? g_bT1 + ((size_t)b * 1024 + nBase) * CCH
                     : (lvl == 2) ? g_bT2 + ((size_t)b * 256 + nBase) * CCH
                                  : g_bT3 + ((size_t)b * 64) * CCH;
    float* Cp = (lvl == 1) ? g_corr1 : (lvl == 2) ? g_corr2 : g_corr3;

    const __half* Ap = g_a + (size_t)b * MQ * CCH + (size_t)mBase * CCH;

    uint32_t aLane[4];
#pragma unroll
    for (int mt = 0; mt < 4; mt++)
        aLane[mt] = (uint32_t)((mWarp + mt * 16 + (lane & 15)) * ROWB
                               + ((lane >> 4) * 8) * 2);
    uint32_t bLane[2];
#pragma unroll
    for (int np = 0; np < 2; np++)
        bLane[np] = (uint32_t)(A_BYTES
                    + (nWarp + np * 16 + (lane & 7) + ((lane >> 4) & 1) * 8) * ROWB
                    + (((lane >> 3) & 1) * 8) * 2);

    float acc[4][4][4];
#pragma unroll
    for (int mt = 0; mt < 4; mt++)
#pragma unroll
        for (int nt2 = 0; nt2 < 4; nt2++)
#pragma unroll
            for (int r = 0; r < 4; r++) acc[mt][nt2][r] = 0.0f;

    auto stage_chunk = [&](int st, int ch) {
        const int k0 = ch * KC;
        const uint32_t abase = sb + st * STAGE_B;
        const uint32_t bbase = abase + A_BYTES;
#pragma unroll
        for (int it = 0; it < 4; it++) {
            int f = tid + 256 * it;
            int row = f >> 3, seg = f & 7;
            cp16(abase + row * ROWB + seg * 16,
                 Ap + (size_t)row * CCH + k0 + seg * 8);
        }
#pragma unroll
        for (int it = 0; it < 4; it++) {
            int f = tid + 256 * it;
            int row = f >> 3, seg = f & 7;
            cp16p(bbase + row * ROWB + seg * 16,
                  Bp + (size_t)row * CCH + k0 + seg * 8,
                  (nBase + row) < Npix);
        }
    };

    stage_chunk(0, 0); CP_COMMIT();
    stage_chunk(1, 1); CP_COMMIT();

    for (int ch = 0; ch < 4; ch++) {
        if (ch < 3) CP_WAIT1(); else CP_WAIT0();
        __syncthreads();
        if (ch + 2 < 4) { stage_chunk((ch + 2) % 3, ch + 2); CP_COMMIT(); }

        const uint32_t stbase = sb + (ch % 3) * STAGE_B;
#pragma unroll
        for (int kk = 0; kk < KC / 16; kk++) {
            uint32_t af[4][4], bf[2][4];
#pragma unroll
            for (int mt = 0; mt < 4; mt++)
                ldsm_x4(af[mt], stbase + aLane[mt] + kk * 32);
#pragma unroll
            for (int np = 0; np < 2; np++)
                ldsm_x4(bf[np], stbase + bLane[np] + kk * 32);
#pragma unroll
            for (int mt = 0; mt < 4; mt++)
#pragma unroll
                for (int np = 0; np < 2; np++) {
                    mma_f16(acc[mt][2 * np],     af[mt], &bf[np][0]);
                    mma_f16(acc[mt][2 * np + 1], af[mt], &bf[np][2]);
                }
        }
    }

    // epilogue: direct write (guard n < Npix for l3 half-tile)
    float* Cb = Cp + ((size_t)(b * MQ + mBase)) * Npix;
#pragma unroll
    for (int mt = 0; mt < 4; mt++) {
#pragma unroll
        for (int nt2 = 0; nt2 < 4; nt2++) {
            int r0 = mWarp + mt * 16 + g;
            int n0 = nBase + nWarp + nt2 * 8 + 2 * tg;
            if (n0 < Npix) {
                *(float2*)&Cb[(size_t)r0 * Npix + n0] =
                    make_float2(acc[mt][nt2][0], acc[mt][nt2][1]);
                *(float2*)&Cb[(size_t)(r0 + 8) * Npix + n0] =
                    make_float2(acc[mt][nt2][2], acc[mt][nt2][3]);
            }
        }
    }
}

// ---------------------------------------------------------------------------
// Kernel 2: level-0 windowed sample. Per query: gather the 10x10 integer
// window's pixel vectors from L2-resident g_bT, dot with fmap1[q] (fp32
// accum), bilinear blend to 81 outputs. 2 queries / 256-thread block.
// ---------------------------------------------------------------------------
#define NQ0 2

__global__ void __launch_bounds__(256)
sample0_kernel(const float* __restrict__ cen, float* __restrict__ out) {
    __shared__ __align__(16) float a1[NQ0][256];
    __shared__ float win[NQ0][100];
    __shared__ int   ixs[NQ0], iys[NQ0];
    __shared__ float fxs[NQ0], fys[NQ0];

    const int tid = threadIdx.x;
    const int q0  = blockIdx.x * NQ0;

    if (tid < NQ0) {
        float cx = cen[(q0 + tid) * 2 + 0];
        float cy = cen[(q0 + tid) * 2 + 1];
        float fl = floorf(cx);
        ixs[tid] = (int)fl; fxs[tid] = cx - fl;
        fl = floorf(cy);
        iys[tid] = (int)fl; fys[tid] = cy - fl;
    }
    // stage fmap1 rows as fp32
    if (tid < NQ0 * 32) {
        int qi = tid >> 5, s = tid & 31;
        uint4 u = *(const uint4*)(g_a + (((size_t)(q0 + qi)) << 8) + s * 8);
        float2 f0 = __half22float2(*(__half2*)&u.x);
        float2 f1 = __half22float2(*(__half2*)&u.y);
        float2 f2 = __half22float2(*(__half2*)&u.z);
        float2 f3 = __half22float2(*(__half2*)&u.w);
        float* d = &a1[qi][s * 8];
        d[0] = f0.x; d[1] = f0.y; d[2] = f1.x; d[3] = f1.y;
        d[4] = f2.x; d[5] = f2.y; d[6] = f3.x; d[7] = f3.y;
    }
    __syncthreads();

    // dot phase: threads (qi, idx<100) -> window pixel (ax, by)
    {
        int qi = tid >> 7, idx = tid & 127;
        if (idx < 100) {
            int ax = idx / 10, by = idx - ax * 10;     // idx = ax*10+by
            int X = ixs[qi] - 4 + ax;
            int Y = iys[qi] - 4 + by;
            float acc = 0.0f;
            if (X >= 0 && X < 64 && Y >= 0 && Y < 64) {
                int q = q0 + qi, bq = q >> 12;
                const uint4* p = (const uint4*)(g_bT +
                    (((size_t)bq * NPIX + (Y << 6) + X) << 8));
                const float4* av = (const float4*)a1[qi];
#pragma unroll 8
                for (int k = 0; k < 32; k++) {
                    uint4 u = p[k];
                    float2 f0 = __half22float2(*(__half2*)&u.x);
                    float2 f1 = __half22float2(*(__half2*)&u.y);
                    float2 f2 = __half22float2(*(__half2*)&u.z);
                    float2 f3 = __half22float2(*(__half2*)&u.w);
                    float4 a0 = av[2 * k], a4 = av[2 * k + 1];
                    acc += f0.x * a0.x + f0.y * a0.y + f1.x * a0.z + f1.y * a0.w
                         + f2.x * a4.x + f2.y * a4.y + f3.x * a4.z + f3.y * a4.w;
                }
            }
            win[qi][idx] = acc;
        }
    }
    __syncthreads();

    // blend phase: 81 channels x NQ0 queries
    if (tid < 81 * NQ0) {
        int qi = tid & (NQ0 - 1);
        int ch = tid >> 1;               // NQ0 == 2
        int i  = ch / 9, j = ch - i * 9;
        float fx = fxs[qi], fy = fys[qi];
        const float* Qb = win[qi];
        float q00 = Qb[i * 10 + j];
        float q10 = Qb[(i + 1) * 10 + j];
        float q01 = Qb[i * 10 + j + 1];
        float q11 = Qb[(i + 1) * 10 + j + 1];
        float val = (1.0f - fy) * ((1.0f - fx) * q00 + fx * q10)
                  +         fy  * ((1.0f - fx) * q01 + fx * q11);
        int q = q0 + qi;
        int bq = q >> 12, m = q & 4095;
        out[((size_t)bq * 324 + ch) * (size_t)MQ + m] = val;
    }
}

// ---------------------------------------------------------------------------
// Kernel 3: sample levels 1..3 from corr1/2/3 (channels 81..323).
// ---------------------------------------------------------------------------
#define SQ 8

__global__ void sample123_kernel(const float* __restrict__ cen, float* __restrict__ out) {
    __shared__ float Qs[3 * SQ * 101];
    __shared__ float fxs[3 * SQ];
    __shared__ float fys[3 * SQ];
    __shared__ float cxy[SQ * 2];

    const int tid = threadIdx.x;
    const int q0  = blockIdx.x * SQ;

    if (tid < SQ * 2) cxy[tid] = cen[q0 * 2 + tid];
    __syncthreads();

    for (int u = tid; u < 3 * SQ * 100; u += 256) {
        int li  = u / (SQ * 100);          // 0..2 -> lvl 1..3
        int lvl = li + 1;
        int rem = u - li * (SQ * 100);
        int qi  = rem / 100;
        int tp  = rem - qi * 100;
        int a   = tp % 10;
        int bb  = tp / 10;

        float sc  = 1.0f / (float)(1 << lvl);
        float cx  = cxy[qi * 2 + 0] * sc;
        float cy  = cxy[qi * 2 + 1] * sc;
        float flx = floorf(cx), fly = floorf(cy);
        int X = (int)flx - 4 + a;
        int Y = (int)fly - 4 + bb;
        int Wl = 64 >> lvl;

        const float* vp = (lvl == 1) ? g_corr1 : (lvl == 2) ? g_corr2 : g_corr3;
        float v = 0.0f;
        if (X >= 0 && X < Wl && Y >= 0 && Y < Wl)
            v = vp[((size_t)(q0 + qi) * Wl + Y) * Wl + X];
        Qs[(li * SQ + qi) * 101 + a * 10 + bb] = v;
        if (tp == 0) {
            fxs[li * SQ + qi] = cx - flx;
            fys[li * SQ + qi] = cy - fly;
        }
    }
    __syncthreads();

    for (int f = tid; f < 243 * SQ; f += 256) {
        int qi = f & (SQ - 1);
        int cl = f / SQ;                   // 0..242
        int li = cl / 81;
        int o  = cl - li * 81;
        int i  = o / 9;
        int j  = o - i * 9;

        float fx = fxs[li * SQ + qi];
        float fy = fys[li * SQ + qi];
        const float* Qb = Qs + (li * SQ + qi) * 101;
        float q00 = Qb[i * 10 + j];
        float q10 = Qb[(i + 1) * 10 + j];
        float q01 = Qb[i * 10 + j + 1];
        float q11 = Qb[(i + 1) * 10 + j + 1];
        float val = (1.0f - fy) * ((1.0f - fx) * q00 + fx * q10)
                  +         fy  * ((1.0f - fx) * q01 + fx * q11);

        int q = q0 + qi;
        int b = q >> 12;
        int m = q & 4095;
        out[((size_t)b * 324 + 81 + cl) * (size_t)MQ + m] = val;
    }
}

// ---------------------------------------------------------------------------
// Launch
// ---------------------------------------------------------------------------
extern "C" void kernel_launch(void* const* d_in, const int* in_sizes, int n_in,
                              void* d_out, int out_size) {
    const float* fmap1 = (const float*)d_in[0];  // (B, M, C)
    const float* fmap2 = (const float*)d_in[1];  // (B, C, H, W)
    const float* cen   = (const float*)d_in[2];  // (B, M, 2)
    float* out         = (float*)d_out;          // (B, 324, M)

    cudaFuncSetAttribute(corr_gemm, cudaFuncAttributeMaxDynamicSharedMemorySize, SMEM_T);

    convA_kernel<<<(BATCH * MQ * CCH / 4) / 256, 256>>>(fmap1);
    transB_kernel<<<dim3(NPIX / 32, CCH / 32, BATCH), dim3(32, 8)>>>(fmap2);
    pyrT_kernel<<<BATCH * CCH, 256>>>(fmap2);
    corr_gemm<<<dim3(11, 32, BATCH), 256, SMEM_T>>>();
    sample0_kernel<<<(BATCH * MQ) / NQ0, 256>>>(cen, out);
    sample123_kernel<<<(BATCH * MQ) / SQ, 256>>>(cen, out);
}

// round 13
// speedup vs baseline: 1.1812x; 1.1812x over previous
#include <cuda_runtime.h>
#include <cuda_fp16.h>
#include <cstdint>

// Problem constants
#define BATCH 2
#define MQ    4096
#define CCH   256
#define NPIX  4096

// -------- scratch (device globals = allowed scratch) --------
__device__ __half g_a[BATCH * MQ * CCH];        // fp16 fmap1 (4 MB)
__device__ __half g_bT[BATCH * NPIX * CCH];     // fp16 fmap2^T (pixel, ch) (4 MB)
__device__ __half g_corr0h[BATCH * MQ * 4096];  // 67 MB  level-0 volume (fp16)
__device__ __half g_corr1h[BATCH * MQ * 1024];  // 16.8 MB (from GEMM epilogue)
__device__ __half g_corr2h[BATCH * MQ * 256];
__device__ __half g_corr3h[BATCH * MQ * 64];

// -------- helpers --------
__device__ __forceinline__ uint32_t smem_u32(const void* p) {
    uint32_t a;
    asm("{ .reg .u64 t; cvta.to.shared.u64 t, %1; cvt.u32.u64 %0, t; }"
        : "=r"(a) : "l"(p));
    return a;
}
__device__ __forceinline__ void cp16(uint32_t dst, const void* src) {
    asm volatile("cp.async.cg.shared.global [%0], [%1], 16;\n"
                 :: "r"(dst), "l"(src));
}
#define CP_COMMIT() asm volatile("cp.async.commit_group;\n" ::: "memory")
#define CP_WAIT1()  asm volatile("cp.async.wait_group 1;\n" ::: "memory")
#define CP_WAIT0()  asm volatile("cp.async.wait_group 0;\n" ::: "memory")

__device__ __forceinline__ void ldsm_x4(uint32_t* r, uint32_t addr) {
    asm volatile("ldmatrix.sync.aligned.m8n8.x4.shared.b16 {%0,%1,%2,%3}, [%4];"
        : "=r"(r[0]), "=r"(r[1]), "=r"(r[2]), "=r"(r[3]) : "r"(addr));
}
__device__ __forceinline__ void mma_f16(float* d, const uint32_t* a, const uint32_t* b) {
    asm volatile(
        "mma.sync.aligned.m16n8k16.row.col.f32.f16.f16.f32 "
        "{%0,%1,%2,%3}, {%4,%5,%6,%7}, {%8,%9}, {%0,%1,%2,%3};\n"
        : "+f"(d[0]), "+f"(d[1]), "+f"(d[2]), "+f"(d[3])
        : "r"(a[0]), "r"(a[1]), "r"(a[2]), "r"(a[3]),
          "r"(b[0]), "r"(b[1]));
}

// ---------------------------------------------------------------------------
// Kernel 0a: fmap1 -> fp16 g_a (elementwise)
// ---------------------------------------------------------------------------
__global__ void convA_kernel(const float* __restrict__ f1) {
    size_t i = ((size_t)blockIdx.x * 256 + threadIdx.x) * 4;
    float4 v = *(const float4*)(f1 + i);
    __half2 lo = __floats2half2_rn(v.x, v.y);
    __half2 hi = __floats2half2_rn(v.z, v.w);
    *(uint2*)&g_a[i] = make_uint2(*(uint32_t*)&lo, *(uint32_t*)&hi);
}

// ---------------------------------------------------------------------------
// Kernel 0b: fmap2 (B, C, NPIX) -> g_bT (B, NPIX, C) fp16, 32x32 SMEM tiles
// ---------------------------------------------------------------------------
__global__ void transB_kernel(const float* __restrict__ f2) {
    __shared__ float tile[32][33];
    const int b  = blockIdx.z;
    const int x0 = blockIdx.x * 32;   // pixel
    const int c0 = blockIdx.y * 32;   // channel
    const int tx = threadIdx.x, ty = threadIdx.y;   // 32 x 8
    const float* src = f2 + (size_t)b * CCH * NPIX;
#pragma unroll
    for (int i = 0; i < 4; i++)
        tile[ty + 8 * i][tx] = src[(size_t)(c0 + ty + 8 * i) * NPIX + x0 + tx];
    __syncthreads();
    __half* dst = g_bT + (size_t)b * NPIX * CCH;
#pragma unroll
    for (int i = 0; i < 4; i++)
        dst[(size_t)(x0 + ty + 8 * i) * CCH + c0 + tx] =
            __float2half_rn(tile[tx][ty + 8 * i]);
}

// ---------------------------------------------------------------------------
// Kernel 1: corr0[b] = A[b] (4096x256) @ B[b]^T, fp16 mma m16n8k16 + ldmatrix.
// CTA tile 128x128, K-chunks of 64, 3-stage cp.async pipeline.
// 8 warps, each 64x32 warp tile (4x4 m16n8). Output fp16; epilogue fuses
// the level-1 pool (computed from fp32 accumulators).
// ---------------------------------------------------------------------------
#define KC 64
#define ROWB 144                          // bytes per SMEM row (64 halves + pad)
#define A_BYTES  (128 * ROWB)
#define B_BYTES  (128 * ROWB)
#define STAGE_B  (A_BYTES + B_BYTES)
#define SMEM_T   (3 * STAGE_B)            // 110592

__global__ void __launch_bounds__(256, 1)
corr_gemm() {
    extern __shared__ char smem[];
    const uint32_t sb = smem_u32(smem);
    const int tid = threadIdx.x;
    const int warpId = tid >> 5, lane = tid & 31;
    const int g  = lane >> 2;
    const int tg = lane & 3;
    const int mWarp = (warpId >> 2) * 64;
    const int nWarp = (warpId & 3) * 32;

    const int b     = blockIdx.z;
    const int mBase = blockIdx.y * 128;
    const int nBase = blockIdx.x * 128;
    const __half* Ap = g_a  + (size_t)b * MQ * CCH + (size_t)mBase * CCH;
    const __half* Bp = g_bT + (size_t)b * NPIX * CCH + (size_t)nBase * CCH;

    uint32_t aLane[4];
#pragma unroll
    for (int mt = 0; mt < 4; mt++)
        aLane[mt] = (uint32_t)((mWarp + mt * 16 + (lane & 15)) * ROWB
                               + ((lane >> 4) * 8) * 2);
    uint32_t bLane[2];
#pragma unroll
    for (int np = 0; np < 2; np++)
        bLane[np] = (uint32_t)(A_BYTES
                    + (nWarp + np * 16 + (lane & 7) + ((lane >> 4) & 1) * 8) * ROWB
                    + (((lane >> 3) & 1) * 8) * 2);

    float acc[4][4][4];
#pragma unroll
    for (int mt = 0; mt < 4; mt++)
#pragma unroll
        for (int nt = 0; nt < 4; nt++)
#pragma unroll
            for (int r = 0; r < 4; r++) acc[mt][nt][r] = 0.0f;

    auto stage_chunk = [&](int st, int ch) {
        const int k0 = ch * KC;
        const uint32_t abase = sb + st * STAGE_B;
        const uint32_t bbase = abase + A_BYTES;
#pragma unroll
        for (int it = 0; it < 4; it++) {
            int f = tid + 256 * it;
            int row = f >> 3, seg = f & 7;
            cp16(abase + row * ROWB + seg * 16,
                 Ap + (size_t)row * CCH + k0 + seg * 8);
        }
#pragma unroll
        for (int it = 0; it < 4; it++) {
            int f = tid + 256 * it;
            int row = f >> 3, seg = f & 7;
            cp16(bbase + row * ROWB + seg * 16,
                 Bp + (size_t)row * CCH + k0 + seg * 8);
        }
    };

    stage_chunk(0, 0); CP_COMMIT();
    stage_chunk(1, 1); CP_COMMIT();

    for (int ch = 0; ch < 4; ch++) {
        if (ch < 3) CP_WAIT1(); else CP_WAIT0();
        __syncthreads();
        if (ch + 2 < 4) { stage_chunk((ch + 2) % 3, ch + 2); CP_COMMIT(); }

        const uint32_t stbase = sb + (ch % 3) * STAGE_B;
#pragma unroll
        for (int kk = 0; kk < KC / 16; kk++) {
            uint32_t af[4][4], bf[2][4];
#pragma unroll
            for (int mt = 0; mt < 4; mt++)
                ldsm_x4(af[mt], stbase + aLane[mt] + kk * 32);
#pragma unroll
            for (int np = 0; np < 2; np++)
                ldsm_x4(bf[np], stbase + bLane[np] + kk * 32);
#pragma unroll
            for (int mt = 0; mt < 4; mt++)
#pragma unroll
                for (int np = 0; np < 2; np++) {
                    mma_f16(acc[mt][2 * np],     af[mt], &bf[np][0]);
                    mma_f16(acc[mt][2 * np + 1], af[mt], &bf[np][2]);
                }
        }
    }
    __syncthreads();   // pipeline done; SMEM reusable for epilogue

    // ---- epilogue: fp16 corr0 write + fp32 tile staging for fused l1 pool ----
    float (*Cs)[132] = (float(*)[132])smem;
    __half* Cb = g_corr0h + ((size_t)(b * MQ + mBase)) * NPIX;
#pragma unroll
    for (int mt = 0; mt < 4; mt++) {
#pragma unroll
        for (int nt = 0; nt < 4; nt++) {
            int r0 = mWarp + mt * 16 + g;
            int c0 = nWarp + nt * 8 + 2 * tg;
            float d0 = acc[mt][nt][0], d1 = acc[mt][nt][1];
            float d2 = acc[mt][nt][2], d3 = acc[mt][nt][3];
            *(__half2*)&Cb[(size_t)r0 * NPIX + nBase + c0] = __floats2half2_rn(d0, d1);
            *(__half2*)&Cb[(size_t)(r0 + 8) * NPIX + nBase + c0] = __floats2half2_rn(d2, d3);
            Cs[r0][c0] = d0;     Cs[r0][c0 + 1] = d1;
            Cs[r0 + 8][c0] = d2; Cs[r0 + 8][c0 + 1] = d3;
        }
    }
    __syncthreads();

    // level-1 pool: N-tile = image rows (nBase/64, nBase/64+1) -> l1 row nBase/128
    {
        const int mL = tid >> 1;
        const int hf = tid & 1;
        const int trow = nBase >> 7;
        __half* C1 = g_corr1h + ((size_t)(b * MQ + mBase + mL)) * 1024 + trow * 32 + hf * 16;
#pragma unroll
        for (int j = 0; j < 16; j += 2) {
            int c0 = 2 * (hf * 16 + j);
            float v0 = 0.25f * (Cs[mL][c0] + Cs[mL][c0 + 1] +
                                Cs[mL][c0 + 64] + Cs[mL][c0 + 65]);
            int c1 = c0 + 2;
            float v1 = 0.25f * (Cs[mL][c1] + Cs[mL][c1 + 1] +
                                Cs[mL][c1 + 64] + Cs[mL][c1 + 65]);
            *(__half2*)&C1[j] = __floats2half2_rn(v0, v1);
        }
    }
}

// ---------------------------------------------------------------------------
// Kernel 2: pool corr1 -> corr2 -> corr3 (fp16 in/out, fp32 pooling math).
// ---------------------------------------------------------------------------
__global__ void pool23_kernel() {
    const int img = blockIdx.x;              // b*MQ + m, 8192 total
    const int tid = threadIdx.x;
    __shared__ float s1[1024];
    __shared__ float s2[256];

    {
        uint2 u = *(const uint2*)(g_corr1h + (size_t)img * 1024 + tid * 4);
        float2 f0 = __half22float2(*(__half2*)&u.x);
        float2 f1 = __half22float2(*(__half2*)&u.y);
        s1[tid * 4 + 0] = f0.x; s1[tid * 4 + 1] = f0.y;
        s1[tid * 4 + 2] = f1.x; s1[tid * 4 + 3] = f1.y;
    }
    __syncthreads();
    {
        int x = tid & 15, y = tid >> 4;
        const float* p = s1 + (2 * y) * 32 + 2 * x;
        float v = 0.25f * (p[0] + p[1] + p[32] + p[33]);
        g_corr2h[(size_t)img * 256 + tid] = __float2half_rn(v);
        s2[tid] = v;
    }
    __syncthreads();
    if (tid < 64) {
        int x = tid & 7, y = tid >> 3;
        const float* p = s2 + (2 * y) * 16 + 2 * x;
        g_corr3h[(size_t)img * 64 + tid] =
            __float2half_rn(0.25f * (p[0] + p[1] + p[16] + p[17]));
    }
}

// ---------------------------------------------------------------------------
// Kernel 3: gather 10x10 integer windows per (query, level), bilinear blend.
// SQ=8 -> 1024 blocks for occupancy. Reads fp16 pyramid.
// ---------------------------------------------------------------------------
#define SQ 8

__global__ void sample_kernel(const float* __restrict__ cen, float* __restrict__ out) {
    __shared__ float Qs[4 * SQ * 101];
    __shared__ float fxs[4 * SQ];
    __shared__ float fys[4 * SQ];
    __shared__ float cxy[SQ * 2];

    const int tid = threadIdx.x;
    const int q0  = blockIdx.x * SQ;

    if (tid < SQ * 2) cxy[tid] = cen[q0 * 2 + tid];
    __syncthreads();

    for (int u = tid; u < 4 * SQ * 100; u += 256) {
        int lvl = u / (SQ * 100);
        int rem = u - lvl * (SQ * 100);
        int qi  = rem / 100;
        int tp  = rem - qi * 100;
        int a   = tp % 10;
        int bb  = tp / 10;

        float sc  = 1.0f / (float)(1 << lvl);
        float cx  = cxy[qi * 2 + 0] * sc;
        float cy  = cxy[qi * 2 + 1] * sc;
        float flx = floorf(cx), fly = floorf(cy);
        int X = (int)flx - 4 + a;
        int Y = (int)fly - 4 + bb;
        int Wl = 64 >> lvl;

        const __half* vp = (lvl == 0) ? g_corr0h : (lvl == 1) ? g_corr1h
                          : (lvl == 2) ? g_corr2h : g_corr3h;
        float v = 0.0f;
        if (X >= 0 && X < Wl && Y >= 0 && Y < Wl)
            v = __half2float(vp[((size_t)(q0 + qi) * Wl + Y) * Wl + X]);
        Qs[(lvl * SQ + qi) * 101 + a * 10 + bb] = v;
        if (tp == 0) {
            fxs[lvl * SQ + qi] = cx - flx;
            fys[lvl * SQ + qi] = cy - fly;
        }
    }
    __syncthreads();

    for (int f = tid; f < 324 * SQ; f += 256) {
        int qi = f & (SQ - 1);
        int ch = f / SQ;
        int lvl = ch / 81;
        int o   = ch - lvl * 81;
        int i   = o / 9;
        int j   = o - i * 9;

        float fx = fxs[lvl * SQ + qi];
        float fy = fys[lvl * SQ + qi];
        const float* Qb = Qs + (lvl * SQ + qi) * 101;
        float q00 = Qb[i * 10 + j];
        float q10 = Qb[(i + 1) * 10 + j];
        float q01 = Qb[i * 10 + j + 1];
        float q11 = Qb[(i + 1) * 10 + j + 1];
        float val = (1.0f - fy) * ((1.0f - fx) * q00 + fx * q10)
                  +         fy  * ((1.0f - fx) * q01 + fx * q11);

        int q = q0 + qi;
        int b = q >> 12;
        int m = q & 4095;
        out[((size_t)b * 324 + ch) * (size_t)MQ + m] = val;
    }
}

// ---------------------------------------------------------------------------
// Launch
// ---------------------------------------------------------------------------
extern "C" void kernel_launch(void* const* d_in, const int* in_sizes, int n_in,
                              void* d_out, int out_size) {
    const float* fmap1 = (const float*)d_in[0];  // (B, M, C)
    const float* fmap2 = (const float*)d_in[1];  // (B, C, H, W)
    const float* cen   = (const float*)d_in[2];  // (B, M, 2)
    float* out         = (float*)d_out;          // (B, 324, M)

    cudaFuncSetAttribute(corr_gemm, cudaFuncAttributeMaxDynamicSharedMemorySize, SMEM_T);

    convA_kernel<<<(BATCH * MQ * CCH / 4) / 256, 256>>>(fmap1);
    transB_kernel<<<dim3(NPIX / 32, CCH / 32, BATCH), dim3(32, 8)>>>(fmap2);
    corr_gemm<<<dim3(32, 32, BATCH), 256, SMEM_T>>>();
    pool23_kernel<<<BATCH * MQ, 256>>>();
    sample_kernel<<<(BATCH * MQ) / SQ, 256>>>(cen, out);
}

// round 14
// speedup vs baseline: 1.3139x; 1.1124x over previous
#include <cuda_runtime.h>
#include <cuda_fp16.h>
#include <cstdint>

// Problem constants
#define BATCH 2
#define MQ    4096
#define CCH   256
#define NPIX  4096

// -------- scratch (device globals = allowed scratch) --------
__device__ __half g_a[BATCH * MQ * CCH];       // fp16 fmap1 (4 MB)
__device__ __half g_bT[BATCH * NPIX * CCH];    // fp16 fmap2^T (pixel, ch) (4 MB)
__device__ float g_corr0[BATCH * MQ * 4096];   // 134 MB level-0 volume
__device__ float g_corr1[BATCH * MQ * 1024];   //  33 MB (from GEMM epilogue)
__device__ float g_corr2[BATCH * MQ * 256];
__device__ float g_corr3[BATCH * MQ * 64];

// -------- helpers --------
__device__ __forceinline__ uint32_t smem_u32(const void* p) {
    uint32_t a;
    asm("{ .reg .u64 t; cvta.to.shared.u64 t, %1; cvt.u32.u64 %0, t; }"
        : "=r"(a) : "l"(p));
    return a;
}
__device__ __forceinline__ void cp16(uint32_t dst, const void* src) {
    asm volatile("cp.async.cg.shared.global [%0], [%1], 16;\n"
                 :: "r"(dst), "l"(src));
}
#define CP_COMMIT() asm volatile("cp.async.commit_group;\n" ::: "memory")
#define CP_WAIT1()  asm volatile("cp.async.wait_group 1;\n" ::: "memory")
#define CP_WAIT0()  asm volatile("cp.async.wait_group 0;\n" ::: "memory")

__device__ __forceinline__ void ldsm_x4(uint32_t* r, uint32_t addr) {
    asm volatile("ldmatrix.sync.aligned.m8n8.x4.shared.b16 {%0,%1,%2,%3}, [%4];"
        : "=r"(r[0]), "=r"(r[1]), "=r"(r[2]), "=r"(r[3]) : "r"(addr));
}
__device__ __forceinline__ void mma_f16(float* d, const uint32_t* a, const uint32_t* b) {
    asm volatile(
        "mma.sync.aligned.m16n8k16.row.col.f32.f16.f16.f32 "
        "{%0,%1,%2,%3}, {%4,%5,%6,%7}, {%8,%9}, {%0,%1,%2,%3};\n"
        : "+f"(d[0]), "+f"(d[1]), "+f"(d[2]), "+f"(d[3])
        : "r"(a[0]), "r"(a[1]), "r"(a[2]), "r"(a[3]),
          "r"(b[0]), "r"(b[1]));
}

// ---------------------------------------------------------------------------
// Kernel 0a: fmap1 -> fp16 g_a (elementwise)
// ---------------------------------------------------------------------------
__global__ void convA_kernel(const float* __restrict__ f1) {
    size_t i = ((size_t)blockIdx.x * 256 + threadIdx.x) * 4;
    float4 v = *(const float4*)(f1 + i);
    __half2 lo = __floats2half2_rn(v.x, v.y);
    __half2 hi = __floats2half2_rn(v.z, v.w);
    *(uint2*)&g_a[i] = make_uint2(*(uint32_t*)&lo, *(uint32_t*)&hi);
}

// ---------------------------------------------------------------------------
// Kernel 0b: fmap2 (B, C, NPIX) -> g_bT (B, NPIX, C) fp16, 32x32 SMEM tiles
// ---------------------------------------------------------------------------
__global__ void transB_kernel(const float* __restrict__ f2) {
    __shared__ float tile[32][33];
    const int b  = blockIdx.z;
    const int x0 = blockIdx.x * 32;   // pixel
    const int c0 = blockIdx.y * 32;   // channel
    const int tx = threadIdx.x, ty = threadIdx.y;   // 32 x 8
    const float* src = f2 + (size_t)b * CCH * NPIX;
#pragma unroll
    for (int i = 0; i < 4; i++)
        tile[ty + 8 * i][tx] = src[(size_t)(c0 + ty + 8 * i) * NPIX + x0 + tx];
    __syncthreads();
    __half* dst = g_bT + (size_t)b * NPIX * CCH;
#pragma unroll
    for (int i = 0; i < 4; i++)
        dst[(size_t)(x0 + ty + 8 * i) * CCH + c0 + tx] =
            __float2half_rn(tile[tx][ty + 8 * i]);
}

// ---------------------------------------------------------------------------
// Kernel 1: corr0[b] = A[b] (4096x256) @ B[b]^T, fp16 mma m16n8k16 + ldmatrix.
// CTA tile 128x128, K-chunks of 32, 3-stage cp.async pipeline, 2 CTAs/SM.
// 8 warps, each 64x32 warp tile (4x4 m16n8). Epilogue fuses level-1 pool.
// Row pitch 80B (5 x 16B, odd mod 8) -> all LDSM phases conflict-free.
// ---------------------------------------------------------------------------
#define KC 32
#define ROWB 80                            // 32 halves (64B) + 16B pad
#define A_BYTES  (128 * ROWB)              // 10240
#define B_BYTES  (128 * ROWB)              // 10240
#define STAGE_B  (A_BYTES + B_BYTES)       // 20480
#define SMEM_T   (128 * 132 * 4)           // 67584 (epilogue tile is the max)

__global__ void __launch_bounds__(256, 2)
corr_gemm() {
    extern __shared__ char smem[];
    const uint32_t sb = smem_u32(smem);
    const int tid = threadIdx.x;
    const int warpId = tid >> 5, lane = tid & 31;
    const int g  = lane >> 2;
    const int tg = lane & 3;
    const int mWarp = (warpId >> 2) * 64;
    const int nWarp = (warpId & 3) * 32;

    const int b     = blockIdx.z;
    const int mBase = blockIdx.y * 128;
    const int nBase = blockIdx.x * 128;
    const __half* Ap = g_a  + (size_t)b * MQ * CCH + (size_t)mBase * CCH;
    const __half* Bp = g_bT + (size_t)b * NPIX * CCH + (size_t)nBase * CCH;

    uint32_t aLane[4];
#pragma unroll
    for (int mt = 0; mt < 4; mt++)
        aLane[mt] = (uint32_t)((mWarp + mt * 16 + (lane & 15)) * ROWB
                               + ((lane >> 4) * 8) * 2);
    uint32_t bLane[2];
#pragma unroll
    for (int np = 0; np < 2; np++)
        bLane[np] = (uint32_t)(A_BYTES
                    + (nWarp + np * 16 + (lane & 7) + ((lane >> 4) & 1) * 8) * ROWB
                    + (((lane >> 3) & 1) * 8) * 2);

    float acc[4][4][4];
#pragma unroll
    for (int mt = 0; mt < 4; mt++)
#pragma unroll
        for (int nt = 0; nt < 4; nt++)
#pragma unroll
            for (int r = 0; r < 4; r++) acc[mt][nt][r] = 0.0f;

    // ---- stage one K-chunk: A 128x32 + B 128x32 halves (64B rows, 4 segs) ----
    auto stage_chunk = [&](int st, int ch) {
        const int k0 = ch * KC;
        const uint32_t abase = sb + st * STAGE_B;
        const uint32_t bbase = abase + A_BYTES;
#pragma unroll
        for (int it = 0; it < 2; it++) {
            int f = tid + 256 * it;
            int row = f >> 2, seg = f & 3;
            cp16(abase + row * ROWB + seg * 16,
                 Ap + (size_t)row * CCH + k0 + seg * 8);
        }
#pragma unroll
        for (int it = 0; it < 2; it++) {
            int f = tid + 256 * it;
            int row = f >> 2, seg = f & 3;
            cp16(bbase + row * ROWB + seg * 16,
                 Bp + (size_t)row * CCH + k0 + seg * 8);
        }
    };

    stage_chunk(0, 0); CP_COMMIT();
    stage_chunk(1, 1); CP_COMMIT();

    for (int ch = 0; ch < 8; ch++) {
        if (ch < 7) CP_WAIT1(); else CP_WAIT0();
        __syncthreads();       // stage ch visible; all warps done with buf (ch+2)%3
        if (ch + 2 < 8) { stage_chunk((ch + 2) % 3, ch + 2); CP_COMMIT(); }

        const uint32_t stbase = sb + (ch % 3) * STAGE_B;
#pragma unroll
        for (int kk = 0; kk < KC / 16; kk++) {
            uint32_t af[4][4], bf[2][4];
#pragma unroll
            for (int mt = 0; mt < 4; mt++)
                ldsm_x4(af[mt], stbase + aLane[mt] + kk * 32);
#pragma unroll
            for (int np = 0; np < 2; np++)
                ldsm_x4(bf[np], stbase + bLane[np] + kk * 32);
#pragma unroll
            for (int mt = 0; mt < 4; mt++)
#pragma unroll
                for (int np = 0; np < 2; np++) {
                    mma_f16(acc[mt][2 * np],     af[mt], &bf[np][0]);
                    mma_f16(acc[mt][2 * np + 1], af[mt], &bf[np][2]);
                }
        }
    }
    __syncthreads();   // pipeline done; SMEM reusable for epilogue

    // ---- epilogue: write corr0 + stage tile for fused level-1 pool ----
    float (*Cs)[132] = (float(*)[132])smem;
    float* Cb = g_corr0 + ((size_t)(b * MQ + mBase)) * NPIX;
#pragma unroll
    for (int mt = 0; mt < 4; mt++) {
#pragma unroll
        for (int nt = 0; nt < 4; nt++) {
            int r0 = mWarp + mt * 16 + g;
            int c0 = nWarp + nt * 8 + 2 * tg;
            float d0 = acc[mt][nt][0], d1 = acc[mt][nt][1];
            float d2 = acc[mt][nt][2], d3 = acc[mt][nt][3];
            *(float2*)&Cb[(size_t)r0 * NPIX + nBase + c0] = make_float2(d0, d1);
            *(float2*)&Cb[(size_t)(r0 + 8) * NPIX + nBase + c0] = make_float2(d2, d3);
            Cs[r0][c0] = d0;     Cs[r0][c0 + 1] = d1;
            Cs[r0 + 8][c0] = d2; Cs[r0 + 8][c0 + 1] = d3;
        }
    }
    __syncthreads();

    // level-1 pool: N-tile = image rows (nBase/64, nBase/64+1) -> l1 row nBase/128
    {
        const int mL = tid >> 1;
        const int hf = tid & 1;
        const int trow = nBase >> 7;
        float* C1 = g_corr1 + ((size_t)(b * MQ + mBase + mL)) * 1024 + trow * 32 + hf * 16;
#pragma unroll
        for (int j4 = 0; j4 < 16; j4 += 4) {
            float4 v;
            float* vo = &v.x;
#pragma unroll
            for (int e = 0; e < 4; e++) {
                int c = 2 * (hf * 16 + j4 + e);
                vo[e] = 0.25f * (Cs[mL][c] + Cs[mL][c + 1] +
                                 Cs[mL][c + 64] + Cs[mL][c + 65]);
            }
            *(float4*)(C1 + j4) = v;
        }
    }
}

// ---------------------------------------------------------------------------
// Kernel 2: pool corr1 -> corr2 -> corr3. One block per (b,m) image.
// ---------------------------------------------------------------------------
__global__ void pool23_kernel() {
    const int img = blockIdx.x;              // b*MQ + m, 8192 total
    const int tid = threadIdx.x;
    __shared__ float s1[1024];
    __shared__ float s2[256];

    *(float4*)&s1[tid * 4] = *(const float4*)(g_corr1 + (size_t)img * 1024 + tid * 4);
    __syncthreads();
    {
        int x = tid & 15, y = tid >> 4;
        const float* p = s1 + (2 * y) * 32 + 2 * x;
        float v = 0.25f * (p[0] + p[1] + p[32] + p[33]);
        g_corr2[(size_t)img * 256 + tid] = v;
        s2[tid] = v;
    }
    __syncthreads();
    if (tid < 64) {
        int x = tid & 7, y = tid >> 3;
        const float* p = s2 + (2 * y) * 16 + 2 * x;
        g_corr3[(size_t)img * 64 + tid] = 0.25f * (p[0] + p[1] + p[16] + p[17]);
    }
}

// ---------------------------------------------------------------------------
// Kernel 3: gather 10x10 integer windows per (query, level), bilinear blend.
// SQ=8 -> 1024 blocks for occupancy.
// ---------------------------------------------------------------------------
#define SQ 8

__global__ void sample_kernel(const float* __restrict__ cen, float* __restrict__ out) {
    __shared__ float Qs[4 * SQ * 101];
    __shared__ float fxs[4 * SQ];
    __shared__ float fys[4 * SQ];
    __shared__ float cxy[SQ * 2];

    const int tid = threadIdx.x;
    const int q0  = blockIdx.x * SQ;

    if (tid < SQ * 2) cxy[tid] = cen[q0 * 2 + tid];
    __syncthreads();

    for (int u = tid; u < 4 * SQ * 100; u += 256) {
        int lvl = u / (SQ * 100);
        int rem = u - lvl * (SQ * 100);
        int qi  = rem / 100;
        int tp  = rem - qi * 100;
        int a   = tp % 10;
        int bb  = tp / 10;

        float sc  = 1.0f / (float)(1 << lvl);
        float cx  = cxy[qi * 2 + 0] * sc;
        float cy  = cxy[qi * 2 + 1] * sc;
        float flx = floorf(cx), fly = floorf(cy);
        int X = (int)flx - 4 + a;
        int Y = (int)fly - 4 + bb;
        int Wl = 64 >> lvl;

        const float* vp = (lvl == 0) ? g_corr0 : (lvl == 1) ? g_corr1
                         : (lvl == 2) ? g_corr2 : g_corr3;
        float v = 0.0f;
        if (X >= 0 && X < Wl && Y >= 0 && Y < Wl)
            v = vp[((size_t)(q0 + qi) * Wl + Y) * Wl + X];
        Qs[(lvl * SQ + qi) * 101 + a * 10 + bb] = v;
        if (tp == 0) {
            fxs[lvl * SQ + qi] = cx - flx;
            fys[lvl * SQ + qi] = cy - fly;
        }
    }
    __syncthreads();

    for (int f = tid; f < 324 * SQ; f += 256) {
        int qi = f & (SQ - 1);
        int ch = f / SQ;
        int lvl = ch / 81;
        int o   = ch - lvl * 81;
        int i   = o / 9;
        int j   = o - i * 9;

        float fx = fxs[lvl * SQ + qi];
        float fy = fys[lvl * SQ + qi];
        const float* Qb = Qs + (lvl * SQ + qi) * 101;
        float q00 = Qb[i * 10 + j];
        float q10 = Qb[(i + 1) * 10 + j];
        float q01 = Qb[i * 10 + j + 1];
        float q11 = Qb[(i + 1) * 10 + j + 1];
        float val = (1.0f - fy) * ((1.0f - fx) * q00 + fx * q10)
                  +         fy  * ((1.0f - fx) * q01 + fx * q11);

        int q = q0 + qi;
        int b = q >> 12;
        int m = q & 4095;
        out[((size_t)b * 324 + ch) * (size_t)MQ + m] = val;
    }
}

// ---------------------------------------------------------------------------
// Launch
// ---------------------------------------------------------------------------
extern "C" void kernel_launch(void* const* d_in, const int* in_sizes, int n_in,
                              void* d_out, int out_size) {
    const float* fmap1 = (const float*)d_in[0];  // (B, M, C)
    const float* fmap2 = (const float*)d_in[1];  // (B, C, H, W)
    const float* cen   = (const float*)d_in[2];  // (B, M, 2)
    float* out         = (float*)d_out;          // (B, 324, M)

    cudaFuncSetAttribute(corr_gemm, cudaFuncAttributeMaxDynamicSharedMemorySize, SMEM_T);

    convA_kernel<<<(BATCH * MQ * CCH / 4) / 256, 256>>>(fmap1);
    transB_kernel<<<dim3(NPIX / 32, CCH / 32, BATCH), dim3(32, 8)>>>(fmap2);
    corr_gemm<<<dim3(32, 32, BATCH), 256, SMEM_T>>>();
    pool23_kernel<<<BATCH * MQ, 256>>>();
    sample_kernel<<<(BATCH * MQ) / SQ, 256>>>(cen, out);
}

// round 15
// speedup vs baseline: 1.9885x; 1.5133x over previous
#include <cuda_runtime.h>
#include <cuda_fp16.h>
#include <cstdint>

// Problem constants
#define BATCH 2
#define MQ    4096
#define CCH   256
#define NPIX  4096
#define SLOTS 1536          // per-bin capacity (mean ~625; 36 sigma headroom)

// -------- scratch (device globals = allowed scratch) --------
__device__ __half g_a[BATCH * MQ * CCH];       // fp16 fmap1 (4 MB)
__device__ __half g_bT[BATCH * NPIX * CCH];    // fp16 fmap2^T (pixel, ch) (4 MB)
__device__ __half g_bT1[BATCH * 1024 * CCH];   // pooled fmap2 pyramid, transposed fp16
__device__ __half g_bT2[BATCH * 256 * CCH];
__device__ __half g_bT3[BATCH * 64 * CCH];
__device__ float g_corr1[BATCH * MQ * 1024];   // full l1..l3 volumes (from GEMM)
__device__ float g_corr2[BATCH * MQ * 256];
__device__ float g_corr3[BATCH * MQ * 64];
__device__ float g_corrW[32 * SLOTS * 256];    // windowed l0: [bin][slot][tilePixel] (50 MB)
__device__ int   g_cnt[32];                    // per-bin query counts
__device__ int   g_idx[32 * SLOTS];            // per-bin query lists
__device__ int   g_qmap[BATCH * MQ * 4];       // per-query (tile<<16)|slot, -1 = unused

// -------- helpers --------
__device__ __forceinline__ uint32_t smem_u32(const void* p) {
    uint32_t a;
    asm("{ .reg .u64 t; cvta.to.shared.u64 t, %1; cvt.u32.u64 %0, t; }"
        : "=r"(a) : "l"(p));
    return a;
}
__device__ __forceinline__ void cp16(uint32_t dst, const void* src) {
    asm volatile("cp.async.cg.shared.global [%0], [%1], 16;\n"
                 :: "r"(dst), "l"(src));
}
__device__ __forceinline__ void cp16p(uint32_t dst, const void* src, bool v) {
    int sz = v ? 16 : 0;
    asm volatile("cp.async.cg.shared.global [%0], [%1], 16, %2;\n"
                 :: "r"(dst), "l"(src), "r"(sz));
}
#define CP_COMMIT() asm volatile("cp.async.commit_group;\n" ::: "memory")
#define CP_WAIT1()  asm volatile("cp.async.wait_group 1;\n" ::: "memory")
#define CP_WAIT0()  asm volatile("cp.async.wait_group 0;\n" ::: "memory")

__device__ __forceinline__ void ldsm_x4(uint32_t* r, uint32_t addr) {
    asm volatile("ldmatrix.sync.aligned.m8n8.x4.shared.b16 {%0,%1,%2,%3}, [%4];"
        : "=r"(r[0]), "=r"(r[1]), "=r"(r[2]), "=r"(r[3]) : "r"(addr));
}
__device__ __forceinline__ void mma_f16(float* d, const uint32_t* a, const uint32_t* b) {
    asm volatile(
        "mma.sync.aligned.m16n8k16.row.col.f32.f16.f16.f32 "
        "{%0,%1,%2,%3}, {%4,%5,%6,%7}, {%8,%9}, {%0,%1,%2,%3};\n"
        : "+f"(d[0]), "+f"(d[1]), "+f"(d[2]), "+f"(d[3])
        : "r"(a[0]), "r"(a[1]), "r"(a[2]), "r"(a[3]),
          "r"(b[0]), "r"(b[1]));
}

// ---------------------------------------------------------------------------
// Kernel Z: zero bin counters (graph-replay safe)
// ---------------------------------------------------------------------------
__global__ void zero_kernel() { g_cnt[threadIdx.x] = 0; }

// ---------------------------------------------------------------------------
// Kernel 0a: fmap1 -> fp16 g_a
// ---------------------------------------------------------------------------
__global__ void convA_kernel(const float* __restrict__ f1) {
    size_t i = ((size_t)blockIdx.x * 256 + threadIdx.x) * 4;
    float4 v = *(const float4*)(f1 + i);
    __half2 lo = __floats2half2_rn(v.x, v.y);
    __half2 hi = __floats2half2_rn(v.z, v.w);
    *(uint2*)&g_a[i] = make_uint2(*(uint32_t*)&lo, *(uint32_t*)&hi);
}

// ---------------------------------------------------------------------------
// Kernel 0b: fmap2 (B, C, NPIX) -> g_bT (B, NPIX, C) fp16
// ---------------------------------------------------------------------------
__global__ void transB_kernel(const float* __restrict__ f2) {
    __shared__ float tile[32][33];
    const int b  = blockIdx.z;
    const int x0 = blockIdx.x * 32;
    const int c0 = blockIdx.y * 32;
    const int tx = threadIdx.x, ty = threadIdx.y;   // 32 x 8
    const float* src = f2 + (size_t)b * CCH * NPIX;
#pragma unroll
    for (int i = 0; i < 4; i++)
        tile[ty + 8 * i][tx] = src[(size_t)(c0 + ty + 8 * i) * NPIX + x0 + tx];
    __syncthreads();
    __half* dst = g_bT + (size_t)b * NPIX * CCH;
#pragma unroll
    for (int i = 0; i < 4; i++)
        dst[(size_t)(x0 + ty + 8 * i) * CCH + c0 + tx] =
            __float2half_rn(tile[tx][ty + 8 * i]);
}

// ---------------------------------------------------------------------------
// Kernel 0c: pooled fmap2 pyramid, transposed fp16 (pool commutes with dot)
// ---------------------------------------------------------------------------
__global__ void pyrT_kernel(const float* __restrict__ f2) {
    const int plane = blockIdx.x;            // b*256 + c
    const int b = plane >> 8, c = plane & 255;
    const float* src = f2 + (size_t)plane * 4096;
    __shared__ float s1[1024];
    __shared__ float s2[256];
    const int tid = threadIdx.x;
#pragma unroll
    for (int i = 0; i < 4; i++) {
        int idx = tid + 256 * i;
        int x = idx & 31, y = idx >> 5;
        const float* p = src + (2 * y) * 64 + 2 * x;
        float v = 0.25f * (p[0] + p[1] + p[64] + p[65]);
        s1[idx] = v;
        g_bT1[((size_t)(b << 10) + idx) * CCH + c] = __float2half_rn(v);
    }
    __syncthreads();
    {
        int x = tid & 15, y = tid >> 4;
        const float* p = s1 + (2 * y) * 32 + 2 * x;
        float v = 0.25f * (p[0] + p[1] + p[32] + p[33]);
        s2[tid] = v;
        g_bT2[((size_t)(b << 8) + tid) * CCH + c] = __float2half_rn(v);
    }
    __syncthreads();
    if (tid < 64) {
        int x = tid & 7, y = tid >> 3;
        const float* p = s2 + (2 * y) * 16 + 2 * x;
        float v = 0.25f * (p[0] + p[1] + p[16] + p[17]);
        g_bT3[((size_t)(b << 6) + tid) * CCH + c] = __float2half_rn(v);
    }
}

// ---------------------------------------------------------------------------
// Kernel 0d: bin queries by the 16x16 image tiles their 10x10 window touches.
// ---------------------------------------------------------------------------
__global__ void binq_kernel(const float* __restrict__ cen) {
    int q = blockIdx.x * 256 + threadIdx.x;          // 0..8191
    float cx = cen[2 * q], cy = cen[2 * q + 1];
    int ix = (int)floorf(cx), iy = (int)floorf(cy);
    int b = q >> 12;
    int tx0 = (ix - 4) >> 4, tx1 = (ix + 5) >> 4;    // arithmetic shift ok
    int ty0 = (iy - 4) >> 4, ty1 = (iy + 5) >> 4;
    int txs[2] = {tx0, tx1}, ntx = (tx1 != tx0) ? 2 : 1;
    int tys[2] = {ty0, ty1}, nty = (ty1 != ty0) ? 2 : 1;
    int qm[4] = {-1, -1, -1, -1};
    int k = 0;
    for (int j = 0; j < nty; j++) {
        int ty = tys[j];
        if (ty < 0 || ty > 3) continue;
        for (int i = 0; i < ntx; i++) {
            int tx = txs[i];
            if (tx < 0 || tx > 3) continue;
            int t = ty * 4 + tx;
            int bin = (b << 4) + t;
            int slot = atomicAdd(&g_cnt[bin], 1);
            g_idx[bin * SLOTS + slot] = q;
            qm[k++] = (t << 16) | slot;
        }
    }
    *(int4*)&g_qmap[q * 4] = make_int4(qm[0], qm[1], qm[2], qm[3]);
}

// ---------------------------------------------------------------------------
// GEMM common: 128x128 CTA tile, fp16 mma m16n8k16 + ldmatrix, KC=32,
// 3-stage cp.async, 2 CTAs/SM. Row pitch 80B -> LDSM conflict-free.
// ---------------------------------------------------------------------------
#define KC 32
#define ROWB 80
#define A_BYTES  (128 * ROWB)
#define B_BYTES  (128 * ROWB)
#define STAGE_B  (A_BYTES + B_BYTES)       // 20480
#define SMEM_W   (3 * STAGE_B)             // 61440

// ---------------------------------------------------------------------------
// Kernel 1: windowed level-0 GEMM. grid (half, slotTile, bin).
// A rows gathered via g_idx; B = one 16x16 image tile (N=128 half-tile).
// ---------------------------------------------------------------------------
__global__ void __launch_bounds__(256, 2)
gemmW_kernel() {
    extern __shared__ char smem[];
    __shared__ int sidx[128];
    const uint32_t sb = smem_u32(smem);
    const int tid = threadIdx.x;
    const int warpId = tid >> 5, lane = tid & 31;
    const int g  = lane >> 2;
    const int tg = lane & 3;
    const int mWarp = (warpId >> 2) * 64;
    const int nWarp = (warpId & 3) * 32;

    const int bin   = blockIdx.z;
    const int half  = blockIdx.x;           // 0/1 -> tile rows 0-7 / 8-15
    const int slot0 = blockIdx.y * 128;
    const int cnt   = g_cnt[bin];
    if (slot0 >= cnt) return;
    const int b  = bin >> 4, t = bin & 15;
    const int tY0 = (t >> 2) * 16, tX0 = (t & 3) * 16;

    if (tid < 128)
        sidx[tid] = g_idx[bin * SLOTS + min(slot0 + tid, cnt - 1)];
    __syncthreads();

    // per-thread staging constants (2 A rows + 2 B rows, 1 seg each)
    const int r0t = tid >> 2, seg = tid & 3;
    const __half* apr0 = g_a + ((size_t)sidx[r0t]) * 256 + seg * 8;
    const __half* apr1 = g_a + ((size_t)sidx[r0t + 64]) * 256 + seg * 8;
    const int py0 = half * 8 + (r0t >> 4), px0 = r0t & 15;                 // p 0..63
    const int py1 = half * 8 + ((r0t + 64) >> 4), px1 = (r0t + 64) & 15;   // p 64..127
    const __half* bpr0 = g_bT + ((size_t)b * 4096 + (tY0 + py0) * 64 + tX0 + px0) * 256 + seg * 8;
    const __half* bpr1 = g_bT + ((size_t)b * 4096 + (tY0 + py1) * 64 + tX0 + px1) * 256 + seg * 8;

    uint32_t aLane[4];
#pragma unroll
    for (int mt = 0; mt < 4; mt++)
        aLane[mt] = (uint32_t)((mWarp + mt * 16 + (lane & 15)) * ROWB
                               + ((lane >> 4) * 8) * 2);
    uint32_t bLane[2];
#pragma unroll
    for (int np = 0; np < 2; np++)
        bLane[np] = (uint32_t)(A_BYTES
                    + (nWarp + np * 16 + (lane & 7) + ((lane >> 4) & 1) * 8) * ROWB
                    + (((lane >> 3) & 1) * 8) * 2);

    float acc[4][4][4];
#pragma unroll
    for (int mt = 0; mt < 4; mt++)
#pragma unroll
        for (int nt = 0; nt < 4; nt++)
#pragma unroll
            for (int r = 0; r < 4; r++) acc[mt][nt][r] = 0.0f;

    auto stage_chunk = [&](int st, int ch) {
        const int k0 = ch * KC;
        const uint32_t abase = sb + st * STAGE_B;
        const uint32_t bbase = abase + A_BYTES;
        cp16(abase + r0t * ROWB + seg * 16,        apr0 + k0);
        cp16(abase + (r0t + 64) * ROWB + seg * 16, apr1 + k0);
        cp16(bbase + r0t * ROWB + seg * 16,        bpr0 + k0);
        cp16(bbase + (r0t + 64) * ROWB + seg * 16, bpr1 + k0);
    };

    stage_chunk(0, 0); CP_COMMIT();
    stage_chunk(1, 1); CP_COMMIT();

    for (int ch = 0; ch < 8; ch++) {
        if (ch < 7) CP_WAIT1(); else CP_WAIT0();
        __syncthreads();
        if (ch + 2 < 8) { stage_chunk((ch + 2) % 3, ch + 2); CP_COMMIT(); }

        const uint32_t stbase = sb + (ch % 3) * STAGE_B;
#pragma unroll
        for (int kk = 0; kk < KC / 16; kk++) {
            uint32_t af[4][4], bf[2][4];
#pragma unroll
            for (int mt = 0; mt < 4; mt++)
                ldsm_x4(af[mt], stbase + aLane[mt] + kk * 32);
#pragma unroll
            for (int np = 0; np < 2; np++)
                ldsm_x4(bf[np], stbase + bLane[np] + kk * 32);
#pragma unroll
            for (int mt = 0; mt < 4; mt++)
#pragma unroll
                for (int np = 0; np < 2; np++) {
                    mma_f16(acc[mt][2 * np],     af[mt], &bf[np][0]);
                    mma_f16(acc[mt][2 * np + 1], af[mt], &bf[np][2]);
                }
        }
    }

    // epilogue: corrW[bin][slot0 + r][half*128 + n]
    float* Cb = g_corrW + ((size_t)bin * SLOTS + slot0) * 256 + half * 128;
#pragma unroll
    for (int mt = 0; mt < 4; mt++) {
#pragma unroll
        for (int nt = 0; nt < 4; nt++) {
            int r0 = mWarp + mt * 16 + g;
            int c0 = nWarp + nt * 8 + 2 * tg;
            *(float2*)&Cb[(size_t)r0 * 256 + c0] =
                make_float2(acc[mt][nt][0], acc[mt][nt][1]);
            *(float2*)&Cb[(size_t)(r0 + 8) * 256 + c0] =
                make_float2(acc[mt][nt][2], acc[mt][nt][3]);
        }
    }
}

// ---------------------------------------------------------------------------
// Kernel 2: levels 1..3 full GEMM vs pooled pyramid.
// grid x: 0-7 -> l1 n-tiles, 8-9 -> l2, 10 -> l3.
// ---------------------------------------------------------------------------
__global__ void __launch_bounds__(256, 2)
gemm123_kernel() {
    extern __shared__ char smem[];
    const uint32_t sb = smem_u32(smem);
    const int tid = threadIdx.x;
    const int warpId = tid >> 5, lane = tid & 31;
    const int g  = lane >> 2;
    const int tg = lane & 3;
    const int mWarp = (warpId >> 2) * 64;
    const int nWarp = (warpId & 3) * 32;

    const int b     = blockIdx.z;
    const int mBase = blockIdx.y * 128;
    const int x = blockIdx.x;
    int lvl, nt;
    if (x < 8)       { lvl = 1; nt = x; }
    else if (x < 10) { lvl = 2; nt = x - 8; }
    else             { lvl = 3; nt = 0; }
    const int Npix = 4096 >> (2 * lvl);
    const int nBase = nt * 128;
    const __half* Bp = (lvl == 1) ? g_bT1 + ((size_t)b * 1024 + nBase) * CCH
                     : (lvl == 2) ? g_bT2 + ((size_t)b * 256 + nBase) * CCH
                                  : g_bT3 + ((size_t)b * 64) * CCH;
    float* Cp = (lvl == 1) ? g_corr1 : (lvl == 2) ? g_corr2 : g_corr3;
    const __half* Ap = g_a + (size_t)b * MQ * CCH + (size_t)mBase * CCH;

    uint32_t aLane[4];
#pragma unroll
    for (int mt = 0; mt < 4; mt++)
        aLane[mt] = (uint32_t)((mWarp + mt * 16 + (lane & 15)) * ROWB
                               + ((lane >> 4) * 8) * 2);
    uint32_t bLane[2];
#pragma unroll
    for (int np = 0; np < 2; np++)
        bLane[np] = (uint32_t)(A_BYTES
                    + (nWarp + np * 16 + (lane & 7) + ((lane >> 4) & 1) * 8) * ROWB
                    + (((lane >> 3) & 1) * 8) * 2);

    float acc[4][4][4];
#pragma unroll
    for (int mt = 0; mt < 4; mt++)
#pragma unroll
        for (int nt2 = 0; nt2 < 4; nt2++)
#pragma unroll
            for (int r = 0; r < 4; r++) acc[mt][nt2][r] = 0.0f;

    const int r0t = tid >> 2, seg = tid & 3;
    auto stage_chunk = [&](int st, int ch) {
        const int k0 = ch * KC;
        const uint32_t abase = sb + st * STAGE_B;
        const uint32_t bbase = abase + A_BYTES;
        cp16(abase + r0t * ROWB + seg * 16,
             Ap + (size_t)r0t * CCH + k0 + seg * 8);
        cp16(abase + (r0t + 64) * ROWB + seg * 16,
             Ap + (size_t)(r0t + 64) * CCH + k0 + seg * 8);
        cp16p(bbase + r0t * ROWB + seg * 16,
              Bp + (size_t)r0t * CCH + k0 + seg * 8, (nBase + r0t) < Npix);
        cp16p(bbase + (r0t + 64) * ROWB + seg * 16,
              Bp + (size_t)(r0t + 64) * CCH + k0 + seg * 8, (nBase + r0t + 64) < Npix);
    };

    stage_chunk(0, 0); CP_COMMIT();
    stage_chunk(1, 1); CP_COMMIT();

    for (int ch = 0; ch < 8; ch++) {
        if (ch < 7) CP_WAIT1(); else CP_WAIT0();
        __syncthreads();
        if (ch + 2 < 8) { stage_chunk((ch + 2) % 3, ch + 2); CP_COMMIT(); }

        const uint32_t stbase = sb + (ch % 3) * STAGE_B;
#pragma unroll
        for (int kk = 0; kk < KC / 16; kk++) {
            uint32_t af[4][4], bf[2][4];
#pragma unroll
            for (int mt = 0; mt < 4; mt++)
                ldsm_x4(af[mt], stbase + aLane[mt] + kk * 32);
#pragma unroll
            for (int np = 0; np < 2; np++)
                ldsm_x4(bf[np], stbase + bLane[np] + kk * 32);
#pragma unroll
            for (int mt = 0; mt < 4; mt++)
#pragma unroll
                for (int np = 0; np < 2; np++) {
                    mma_f16(acc[mt][2 * np],     af[mt], &bf[np][0]);
                    mma_f16(acc[mt][2 * np + 1], af[mt], &bf[np][2]);
                }
        }
    }

    float* Cb = Cp + ((size_t)(b * MQ + mBase)) * Npix;
#pragma unroll
    for (int mt = 0; mt < 4; mt++) {
#pragma unroll
        for (int nt2 = 0; nt2 < 4; nt2++) {
            int r0 = mWarp + mt * 16 + g;
            int n0 = nBase + nWarp + nt2 * 8 + 2 * tg;
            if (n0 < Npix) {
                *(float2*)&Cb[(size_t)r0 * Npix + n0] =
                    make_float2(acc[mt][nt2][0], acc[mt][nt2][1]);
                *(float2*)&Cb[(size_t)(r0 + 8) * Npix + n0] =
                    make_float2(acc[mt][nt2][2], acc[mt][nt2][3]);
            }
        }
    }
}

// ---------------------------------------------------------------------------
// Kernel 3: sampler. l0 taps via per-query slot lookup into g_corrW; l1-3
// taps from full volumes. Bilinear blend to 324 channels.
// ---------------------------------------------------------------------------
#define SQ 8

__global__ void sample_kernel(const float* __restrict__ cen, float* __restrict__ out) {
    __shared__ float Qs[4 * SQ * 101];
    __shared__ float fxs[4 * SQ];
    __shared__ float fys[4 * SQ];
    __shared__ float cxy[SQ * 2];
    __shared__ int   qm[SQ * 4];

    const int tid = threadIdx.x;
    const int q0  = blockIdx.x * SQ;

    if (tid < SQ * 2) cxy[tid] = cen[q0 * 2 + tid];
    if (tid < SQ * 4) qm[tid] = g_qmap[q0 * 4 + tid];
    __syncthreads();

    for (int u = tid; u < 4 * SQ * 100; u += 256) {
        int lvl = u / (SQ * 100);
        int rem = u - lvl * (SQ * 100);
        int qi  = rem / 100;
        int tp  = rem - qi * 100;
        int a   = tp % 10;
        int bb  = tp / 10;

        float sc  = 1.0f / (float)(1 << lvl);
        float cx  = cxy[qi * 2 + 0] * sc;
        float cy  = cxy[qi * 2 + 1] * sc;
        float flx = floorf(cx), fly = floorf(cy);
        int X = (int)flx - 4 + a;
        int Y = (int)fly - 4 + bb;
        int Wl = 64 >> lvl;

        float v = 0.0f;
        if (X >= 0 && X < Wl && Y >= 0 && Y < Wl) {
            if (lvl == 0) {
                int t = ((Y >> 4) << 2) + (X >> 4);
                int slot = 0;
#pragma unroll
                for (int k2 = 0; k2 < 4; k2++) {
                    int e = qm[qi * 4 + k2];
                    if ((e >> 16) == t) slot = e & 0xFFFF;
                }
                int bq = (q0 + qi) >> 12;
                v = g_corrW[(((size_t)((bq << 4) + t)) * SLOTS + slot) * 256
                            + ((Y & 15) << 4) + (X & 15)];
            } else {
                const float* vp = (lvl == 1) ? g_corr1 : (lvl == 2) ? g_corr2 : g_corr3;
                v = vp[((size_t)(q0 + qi) * Wl + Y) * Wl + X];
            }
        }
        Qs[(lvl * SQ + qi) * 101 + a * 10 + bb] = v;
        if (tp == 0) {
            fxs[lvl * SQ + qi] = cx - flx;
            fys[lvl * SQ + qi] = cy - fly;
        }
    }
    __syncthreads();

    for (int f = tid; f < 324 * SQ; f += 256) {
        int qi = f & (SQ - 1);
        int ch = f / SQ;
        int lvl = ch / 81;
        int o   = ch - lvl * 81;
        int i   = o / 9;
        int j   = o - i * 9;

        float fx = fxs[lvl * SQ + qi];
        float fy = fys[lvl * SQ + qi];
        const float* Qb = Qs + (lvl * SQ + qi) * 101;
        float q00 = Qb[i * 10 + j];
        float q10 = Qb[(i + 1) * 10 + j];
        float q01 = Qb[i * 10 + j + 1];
        float q11 = Qb[(i + 1) * 10 + j + 1];
        float val = (1.0f - fy) * ((1.0f - fx) * q00 + fx * q10)
                  +         fy  * ((1.0f - fx) * q01 + fx * q11);

        int q = q0 + qi;
        int b = q >> 12;
        int m = q & 4095;
        out[((size_t)b * 324 + ch) * (size_t)MQ + m] = val;
    }
}

// ---------------------------------------------------------------------------
// Launch
// ---------------------------------------------------------------------------
extern "C" void kernel_launch(void* const* d_in, const int* in_sizes, int n_in,
                              void* d_out, int out_size) {
    const float* fmap1 = (const float*)d_in[0];  // (B, M, C)
    const float* fmap2 = (const float*)d_in[1];  // (B, C, H, W)
    const float* cen   = (const float*)d_in[2];  // (B, M, 2)
    float* out         = (float*)d_out;          // (B, 324, M)

    cudaFuncSetAttribute(gemmW_kernel,   cudaFuncAttributeMaxDynamicSharedMemorySize, SMEM_W);
    cudaFuncSetAttribute(gemm123_kernel, cudaFuncAttributeMaxDynamicSharedMemorySize, SMEM_W);

    zero_kernel<<<1, 32>>>();
    convA_kernel<<<(BATCH * MQ * CCH / 4) / 256, 256>>>(fmap1);
    transB_kernel<<<dim3(NPIX / 32, CCH / 32, BATCH), dim3(32, 8)>>>(fmap2);
    pyrT_kernel<<<BATCH * CCH, 256>>>(fmap2);
    binq_kernel<<<32, 256>>>(cen);
    gemmW_kernel<<<dim3(2, SLOTS / 128, 32), 256, SMEM_W>>>();
    gemm123_kernel<<<dim3(11, 32, BATCH), 256, SMEM_W>>>();
    sample_kernel<<<(BATCH * MQ) / SQ, 256>>>(cen, out);
}